// round 5
// baseline (speedup 1.0000x reference)
#include <cuda_runtime.h>
#include <cuda_bf16.h>

#define N_NODES 50000
#define N_EDGES 800000
#define VOCAB   4096
#define EMB_DIM 128
#define H2      256      // 2*HIDDEN
#define HIDDEN  128
#define N_POS   1024

#define SCAN_BS 512
#define SCAN_NB ((N_NODES + SCAN_BS - 1) / SCAN_BS)

// ---------------- scratch (static device globals; no allocation) ------------
__device__ float g_embW1[VOCAB * H2];        // emb @ W1  (4 MB, L2-resident)
__device__ float g_h1[N_NODES * H2];         // relu(gcn1) (51.2 MB)
__device__ int   g_deg[N_NODES];
__device__ int   g_cur[N_NODES];
__device__ int   g_off[N_NODES + 1];
__device__ float g_dinv[N_NODES];
__device__ int   g_rowi[N_EDGES];
__device__ int   g_xrow[N_EDGES];
__device__ float g_w[N_EDGES];
__device__ int   g_bsum[SCAN_NB];
__device__ float g_abar[H2];                 // mean over selected of agg256
__device__ float g_zbar[HIDDEN];

// ---------------- kernels ----------------------------------------------------

__global__ void k_init() {
    int i = blockIdx.x * blockDim.x + threadIdx.x;
    int stride = gridDim.x * blockDim.x;
    for (int j = i; j < N_NODES; j += stride) { g_deg[j] = 0; g_cur[j] = 0; }
    for (int j = i; j < H2; j += stride) g_abar[j] = 0.f;
}

// embW1 = emb(4096x128) @ W1(128x256). 16 vocab rows per block, 256 threads.
__global__ void k_embW1(const float* __restrict__ emb, const float* __restrict__ W1) {
    __shared__ float se[16 * EMB_DIM];        // 8 KB
    int b = blockIdx.x;                        // 256 blocks
    int t = threadIdx.x;                       // 256 threads (output col)
    for (int i = t; i < 16 * EMB_DIM; i += 256)
        se[i] = emb[b * 16 * EMB_DIM + i];
    __syncthreads();
    float acc[16];
#pragma unroll
    for (int r = 0; r < 16; ++r) acc[r] = 0.f;
#pragma unroll 4
    for (int k = 0; k < EMB_DIM; ++k) {
        float wv = W1[k * H2 + t];
#pragma unroll
        for (int r = 0; r < 16; ++r)
            acc[r] += se[r * EMB_DIM + k] * wv;
    }
#pragma unroll
    for (int r = 0; r < 16; ++r)
        g_embW1[(b * 16 + r) * H2 + t] = acc[r];
}

__global__ void k_degcnt(const int* __restrict__ ei) {
    int e = blockIdx.x * blockDim.x + threadIdx.x;
    if (e < N_EDGES) atomicAdd(&g_deg[ei[N_EDGES + e]], 1);   // col
}

__global__ void k_dinv() {
    int v = blockIdx.x * blockDim.x + threadIdx.x;
    if (v < N_NODES) g_dinv[v] = rsqrtf((float)(g_deg[v] + 1)); // +1 self loop
}

__global__ void k_scan_a() {
    __shared__ int s[SCAN_BS];
    int t = threadIdx.x;
    int i = blockIdx.x * SCAN_BS + t;
    int v = (i < N_NODES) ? g_deg[i] : 0;
    s[t] = v;
    __syncthreads();
    for (int d = 1; d < SCAN_BS; d <<= 1) {
        int tmp = (t >= d) ? s[t - d] : 0;
        __syncthreads();
        s[t] += tmp;
        __syncthreads();
    }
    if (i < N_NODES) g_off[i] = s[t] - v;     // exclusive
    if (t == SCAN_BS - 1) g_bsum[blockIdx.x] = s[t];
}

__global__ void k_scan_b() {
    if (threadIdx.x == 0) {
        int run = 0;
        for (int b = 0; b < SCAN_NB; ++b) { int x = g_bsum[b]; g_bsum[b] = run; run += x; }
        g_off[N_NODES] = run;                 // == N_EDGES
    }
}

__global__ void k_scan_c() {
    int i = blockIdx.x * SCAN_BS + threadIdx.x;
    if (i < N_NODES) g_off[i] += g_bsum[blockIdx.x];
}

__global__ void k_scatter(const int* __restrict__ ei, const int* __restrict__ x) {
    int e = blockIdx.x * blockDim.x + threadIdx.x;
    if (e < N_EDGES) {
        int r = ei[e];
        int c = ei[N_EDGES + e];
        int p = g_off[c] + atomicAdd(&g_cur[c], 1);
        g_rowi[p] = r;
        g_xrow[p] = x[r];
        g_w[p]    = g_dinv[r] * g_dinv[c];
    }
}

// Layer 1: h1[v] = relu( sum_in embW1[x[row]]*norm + embW1[x[v]]*dinv^2 + b1 )
__global__ void k_agg1(const int* __restrict__ x, const float* __restrict__ b1) {
    __shared__ int   sxr[256];
    __shared__ float sw[256];
    int v = blockIdx.x;
    int t = threadIdx.x;                      // 256 = H2 dims
    int beg = g_off[v], end = g_off[v + 1];
    float acc = 0.f;
    for (int base = beg; base < end; base += 256) {
        int m = min(256, end - base);
        __syncthreads();
        if (t < m) { sxr[t] = g_xrow[base + t]; sw[t] = g_w[base + t]; }
        __syncthreads();
#pragma unroll 4
        for (int i = 0; i < m; ++i)
            acc += g_embW1[sxr[i] * H2 + t] * sw[i];
    }
    float dv = g_dinv[v];
    acc += g_embW1[x[v] * H2 + t] * (dv * dv);
    acc += b1[t];
    g_h1[v * H2 + t] = fmaxf(acc, 0.f);
}

// Layer 2 (selected nodes only, commuted): abar = (1/N_POS) * sum_p agg256[pos[p]]
__global__ void k_agg2(const int* __restrict__ pos) {
    __shared__ int   srw[256];
    __shared__ float sw[256];
    int p = blockIdx.x;                       // 1024 blocks
    int t = threadIdx.x;                      // 256 dims
    int v = pos[p];
    int beg = g_off[v], end = g_off[v + 1];
    float acc = 0.f;
    for (int base = beg; base < end; base += 256) {
        int m = min(256, end - base);
        __syncthreads();
        if (t < m) { srw[t] = g_rowi[base + t]; sw[t] = g_w[base + t]; }
        __syncthreads();
#pragma unroll 4
        for (int i = 0; i < m; ++i)
            acc += g_h1[srw[i] * H2 + t] * sw[i];
    }
    float dv = g_dinv[v];
    acc += g_h1[v * H2 + t] * (dv * dv);
    atomicAdd(&g_abar[t], acc * (1.f / N_POS));
}

// zbar = abar @ W2 + b2   (256x128 matvec)
__global__ void k_finalA(const float* __restrict__ W2, const float* __restrict__ b2) {
    int j = threadIdx.x;                      // 128
    float acc = b2[j];
#pragma unroll 8
    for (int k = 0; k < H2; ++k)
        acc += g_abar[k] * W2[k * HIDDEN + j];
    g_zbar[j] = acc;
}

// out = zbar @ Wc + bc    (128x4096 matvec)
__global__ void k_finalB(const float* __restrict__ Wc, const float* __restrict__ bc,
                         float* __restrict__ out) {
    __shared__ float sz[HIDDEN];
    int t = threadIdx.x;
    int c = blockIdx.x * 256 + t;
    if (t < HIDDEN) sz[t] = g_zbar[t];
    __syncthreads();
    float acc = bc[c];
#pragma unroll 8
    for (int j = 0; j < HIDDEN; ++j)
        acc += sz[j] * Wc[j * VOCAB + c];
    out[c] = acc;
}

// ---------------- launch ------------------------------------------------------

extern "C" void kernel_launch(void* const* d_in, const int* in_sizes, int n_in,
                              void* d_out, int out_size) {
    const int*   x    = (const int*)  d_in[0];   // (N_NODES,1) int32
    const int*   ei   = (const int*)  d_in[1];   // (2,N_EDGES) int32
    const int*   pos  = (const int*)  d_in[2];   // (N_POS,)    int32
    const float* emb  = (const float*)d_in[3];   // (4096,128)
    const float* W1   = (const float*)d_in[4];   // (128,256)
    const float* b1   = (const float*)d_in[5];   // (256,)
    const float* W2   = (const float*)d_in[6];   // (256,128)
    const float* b2   = (const float*)d_in[7];   // (128,)
    const float* Wc   = (const float*)d_in[8];   // (128,4096)
    const float* bc   = (const float*)d_in[9];   // (4096,)
    float* out = (float*)d_out;                  // (1,4096)

    k_init<<<256, 256>>>();
    k_embW1<<<VOCAB / 16, 256>>>(emb, W1);
    k_degcnt<<<(N_EDGES + 255) / 256, 256>>>(ei);
    k_dinv<<<(N_NODES + 255) / 256, 256>>>();
    k_scan_a<<<SCAN_NB, SCAN_BS>>>();
    k_scan_b<<<1, 32>>>();
    k_scan_c<<<SCAN_NB, SCAN_BS>>>();
    k_scatter<<<(N_EDGES + 255) / 256, 256>>>(ei, x);
    k_agg1<<<N_NODES, 256>>>(x, b1);
    k_agg2<<<N_POS, 256>>>(pos);
    k_finalA<<<1, HIDDEN>>>(W2, b2);
    k_finalB<<<VOCAB / 256, 256>>>(Wc, bc, out);
}

// round 6
// speedup vs baseline: 1.5944x; 1.5944x over previous
#include <cuda_runtime.h>
#include <cuda_bf16.h>

#define N_NODES 50000
#define N_EDGES 800000
#define VOCAB   4096
#define EMB_DIM 128
#define H2      256      // 2*HIDDEN
#define HIDDEN  128
#define N_POS   1024
#define NPART   64

#define SCAN_BS 512
#define SCAN_NB ((N_NODES + SCAN_BS - 1) / SCAN_BS)

// ---------------- scratch (static device globals; no allocation) ------------
__device__ float g_embW1[VOCAB * H2];        // emb @ W1  (4 MB, L2-resident)
__device__ int   g_deg[N_NODES];
__device__ int   g_cur[N_NODES];
__device__ int   g_off[N_NODES + 1];
__device__ float g_dinv[N_NODES];
__device__ int   g_rowi[N_EDGES];
__device__ int   g_xrow[N_EDGES];
__device__ float g_w[N_EDGES];
__device__ int   g_bsum[SCAN_NB];
__device__ float g_coef[N_NODES];            // sparse coefficients c[u]
__device__ int   g_list[N_NODES];            // compacted nonzero-coef nodes
__device__ int   g_nlist;
__device__ float g_abarp[NPART * H2];        // partial abar accumulators
__device__ float g_zbar[HIDDEN];

// ---------------- kernels ----------------------------------------------------

__global__ void k_init() {
    int i = blockIdx.x * blockDim.x + threadIdx.x;
    int stride = gridDim.x * blockDim.x;
    for (int j = i; j < N_NODES; j += stride) {
        g_deg[j] = 0; g_cur[j] = 0; g_coef[j] = 0.f;
    }
    for (int j = i; j < NPART * H2; j += stride) g_abarp[j] = 0.f;
    if (i == 0) g_nlist = 0;
}

// embW1 = emb(4096x128) @ W1(128x256). 16 vocab rows per block, 256 threads.
__global__ void k_embW1(const float* __restrict__ emb, const float* __restrict__ W1) {
    __shared__ float se[16 * EMB_DIM];        // 8 KB
    int b = blockIdx.x;                        // 256 blocks
    int t = threadIdx.x;                       // 256 threads (output col)
    for (int i = t; i < 16 * EMB_DIM; i += 256)
        se[i] = emb[b * 16 * EMB_DIM + i];
    __syncthreads();
    float acc[16];
#pragma unroll
    for (int r = 0; r < 16; ++r) acc[r] = 0.f;
    for (int k = 0; k < EMB_DIM; k += 4) {
        float w0 = W1[(k + 0) * H2 + t];
        float w1 = W1[(k + 1) * H2 + t];
        float w2 = W1[(k + 2) * H2 + t];
        float w3 = W1[(k + 3) * H2 + t];
#pragma unroll
        for (int r = 0; r < 16; ++r) {
            float4 s = *reinterpret_cast<const float4*>(&se[r * EMB_DIM + k]);
            acc[r] += s.x * w0 + s.y * w1 + s.z * w2 + s.w * w3;
        }
    }
#pragma unroll
    for (int r = 0; r < 16; ++r)
        g_embW1[(b * 16 + r) * H2 + t] = acc[r];
}

__global__ void k_degcnt(const int* __restrict__ ei) {
    int e = blockIdx.x * blockDim.x + threadIdx.x;
    if (e < N_EDGES) atomicAdd(&g_deg[ei[N_EDGES + e]], 1);   // col
}

__global__ void k_dinv() {
    int v = blockIdx.x * blockDim.x + threadIdx.x;
    if (v < N_NODES) g_dinv[v] = rsqrtf((float)(g_deg[v] + 1)); // +1 self loop
}

__global__ void k_scan_a() {
    __shared__ int s[SCAN_BS];
    int t = threadIdx.x;
    int i = blockIdx.x * SCAN_BS + t;
    int v = (i < N_NODES) ? g_deg[i] : 0;
    s[t] = v;
    __syncthreads();
    for (int d = 1; d < SCAN_BS; d <<= 1) {
        int tmp = (t >= d) ? s[t - d] : 0;
        __syncthreads();
        s[t] += tmp;
        __syncthreads();
    }
    if (i < N_NODES) g_off[i] = s[t] - v;     // exclusive
    if (t == SCAN_BS - 1) g_bsum[blockIdx.x] = s[t];
}

__global__ void k_scan_b() {
    if (threadIdx.x == 0) {
        int run = 0;
        for (int b = 0; b < SCAN_NB; ++b) { int x = g_bsum[b]; g_bsum[b] = run; run += x; }
        g_off[N_NODES] = run;                 // == N_EDGES
    }
}

__global__ void k_scan_c() {
    int i = blockIdx.x * SCAN_BS + threadIdx.x;
    if (i < N_NODES) g_off[i] += g_bsum[blockIdx.x];
}

__global__ void k_scatter(const int* __restrict__ ei, const int* __restrict__ x) {
    int e = blockIdx.x * blockDim.x + threadIdx.x;
    if (e < N_EDGES) {
        int r = ei[e];
        int c = ei[N_EDGES + e];
        int p = g_off[c] + atomicAdd(&g_cur[c], 1);
        g_rowi[p] = r;
        g_xrow[p] = x[r];
        g_w[p]    = g_dinv[r] * g_dinv[c];
    }
}

// Coefficients: abar = sum_u c[u] * h1[u]; c from edges into selected + self.
__global__ void k_coef(const int* __restrict__ pos) {
    int p = blockIdx.x;                       // 1024 blocks, 32 threads
    int t = threadIdx.x;
    int v = pos[p];
    int beg = g_off[v], end = g_off[v + 1];
    const float inv = 1.f / N_POS;
    for (int e = beg + t; e < end; e += 32)
        atomicAdd(&g_coef[g_rowi[e]], g_w[e] * inv);
    if (t == 0) {
        float dv = g_dinv[v];
        atomicAdd(&g_coef[v], dv * dv * inv);
    }
}

__global__ void k_compact() {
    int v = blockIdx.x * blockDim.x + threadIdx.x;
    if (v < N_NODES && g_coef[v] != 0.f) {
        int idx = atomicAdd(&g_nlist, 1);
        g_list[idx] = v;
    }
}

// For each needed node u: h1[u] = relu(CSR-agg of embW1 + self + b1), fused
// into partial abar accumulation. 64 threads, float4 over 256 dims.
__global__ void k_h1abar(const int* __restrict__ x, const float* __restrict__ b1) {
    __shared__ int   sxr[64];
    __shared__ float sw[64];
    __shared__ int s_v;
    __shared__ float s_cv;
    int t = threadIdx.x;
    if (t == 0) {
        int n = g_nlist;
        if ((int)blockIdx.x < n) {
            int v = g_list[blockIdx.x];
            s_v = v; s_cv = g_coef[v];
        } else s_v = -1;
    }
    __syncthreads();
    int v = s_v;
    if (v < 0) return;
    float cv = s_cv;

    int beg = g_off[v], end = g_off[v + 1];
    float4 acc = make_float4(0.f, 0.f, 0.f, 0.f);
    for (int base = beg; base < end; base += 64) {
        int m = min(64, end - base);
        __syncthreads();
        if (t < m) { sxr[t] = g_xrow[base + t]; sw[t] = g_w[base + t]; }
        __syncthreads();
        for (int i = 0; i < m; ++i) {
            float4 e = *reinterpret_cast<const float4*>(&g_embW1[sxr[i] * H2 + 4 * t]);
            float wv = sw[i];
            acc.x += e.x * wv; acc.y += e.y * wv;
            acc.z += e.z * wv; acc.w += e.w * wv;
        }
    }
    // self loop
    float dv = g_dinv[v];
    float sl = dv * dv;
    float4 es = *reinterpret_cast<const float4*>(&g_embW1[x[v] * H2 + 4 * t]);
    acc.x += es.x * sl; acc.y += es.y * sl; acc.z += es.z * sl; acc.w += es.w * sl;
    float4 bb = *reinterpret_cast<const float4*>(&b1[4 * t]);
    acc.x = fmaxf(acc.x + bb.x, 0.f) * cv;
    acc.y = fmaxf(acc.y + bb.y, 0.f) * cv;
    acc.z = fmaxf(acc.z + bb.z, 0.f) * cv;
    acc.w = fmaxf(acc.w + bb.w, 0.f) * cv;
    float* dst = &g_abarp[(blockIdx.x & (NPART - 1)) * H2 + 4 * t];
    atomicAdd(dst + 0, acc.x);
    atomicAdd(dst + 1, acc.y);
    atomicAdd(dst + 2, acc.z);
    atomicAdd(dst + 3, acc.w);
}

// Reduce partials, then zbar = abar @ W2 + b2   (256x128 matvec)
__global__ void k_finalA(const float* __restrict__ W2, const float* __restrict__ b2) {
    __shared__ float sabar[H2];
    int t = threadIdx.x;                      // 256
    float s = 0.f;
#pragma unroll 8
    for (int p = 0; p < NPART; ++p)
        s += g_abarp[p * H2 + t];
    sabar[t] = s;
    __syncthreads();
    if (t < HIDDEN) {
        float acc = b2[t];
#pragma unroll 8
        for (int k = 0; k < H2; ++k)
            acc += sabar[k] * W2[k * HIDDEN + t];
        g_zbar[t] = acc;
    }
}

// out = zbar @ Wc + bc    (128x4096 matvec)
__global__ void k_finalB(const float* __restrict__ Wc, const float* __restrict__ bc,
                         float* __restrict__ out) {
    __shared__ float sz[HIDDEN];
    int t = threadIdx.x;
    int c = blockIdx.x * 256 + t;
    if (t < HIDDEN) sz[t] = g_zbar[t];
    __syncthreads();
    float acc = bc[c];
#pragma unroll 8
    for (int j = 0; j < HIDDEN; ++j)
        acc += sz[j] * Wc[j * VOCAB + c];
    out[c] = acc;
}

// ---------------- launch ------------------------------------------------------

extern "C" void kernel_launch(void* const* d_in, const int* in_sizes, int n_in,
                              void* d_out, int out_size) {
    const int*   x    = (const int*)  d_in[0];   // (N_NODES,1) int32
    const int*   ei   = (const int*)  d_in[1];   // (2,N_EDGES) int32
    const int*   pos  = (const int*)  d_in[2];   // (N_POS,)    int32
    const float* emb  = (const float*)d_in[3];   // (4096,128)
    const float* W1   = (const float*)d_in[4];   // (128,256)
    const float* b1   = (const float*)d_in[5];   // (256,)
    const float* W2   = (const float*)d_in[6];   // (256,128)
    const float* b2   = (const float*)d_in[7];   // (128,)
    const float* Wc   = (const float*)d_in[8];   // (128,4096)
    const float* bc   = (const float*)d_in[9];   // (4096,)
    float* out = (float*)d_out;                  // (1,4096)

    k_init<<<256, 256>>>();
    k_embW1<<<VOCAB / 16, 256>>>(emb, W1);
    k_degcnt<<<(N_EDGES + 255) / 256, 256>>>(ei);
    k_dinv<<<(N_NODES + 255) / 256, 256>>>();
    k_scan_a<<<SCAN_NB, SCAN_BS>>>();
    k_scan_b<<<1, 32>>>();
    k_scan_c<<<SCAN_NB, SCAN_BS>>>();
    k_scatter<<<(N_EDGES + 255) / 256, 256>>>(ei, x);
    k_coef<<<N_POS, 32>>>(pos);
    k_compact<<<(N_NODES + 255) / 256, 256>>>();
    k_h1abar<<<N_NODES, 64>>>(x, b1);
    k_finalA<<<1, H2>>>(W2, b2);
    k_finalB<<<VOCAB / 256, 256>>>(Wc, bc, out);
}

// round 7
// speedup vs baseline: 1.7341x; 1.0877x over previous
#include <cuda_runtime.h>
#include <cuda_bf16.h>

#define N_NODES 50000
#define N_EDGES 800000
#define VOCAB   4096
#define EMB_DIM 128
#define H2      256      // 2*HIDDEN
#define HIDDEN  128
#define N_POS   1024
#define NPART   64
#define AGG_GRID 2048
#define INVP    (1.f / N_POS)

// ---------------- scratch (static device globals; no allocation) ------------
__device__ float g_embW1[VOCAB * H2];        // emb @ W1  (4 MB, L2-resident)
__device__ int   g_deg[N_NODES];
__device__ int   g_selcnt[N_NODES];          // multiplicity of node in pos[]
__device__ float g_coef[N_NODES];            // sparse coefficients c[u]
__device__ int   g_needidx[N_NODES];         // node -> compact idx, or -1
__device__ int   g_list[N_NODES];            // compacted nonzero-coef nodes
__device__ int   g_cur[N_NODES];             // per-needed-node fill cursor
__device__ int   g_noff[N_NODES + 1];        // offsets for needed-node CSR
__device__ int   g_nlist;
__device__ int   g_xrow2[N_EDGES];           // vocab id of source, needed edges
__device__ float g_w2[N_EDGES];              // edge weight, needed edges
__device__ float g_abarp[NPART * H2];        // partial abar accumulators
__device__ float g_zbar[HIDDEN];

// ---------------- kernels ----------------------------------------------------

__global__ void k_init() {
    int i = blockIdx.x * blockDim.x + threadIdx.x;
    int stride = gridDim.x * blockDim.x;
    for (int j = i; j < N_NODES; j += stride) {
        g_deg[j] = 0; g_selcnt[j] = 0; g_coef[j] = 0.f;
        g_needidx[j] = -1; g_cur[j] = 0;
    }
    for (int j = i; j < NPART * H2; j += stride) g_abarp[j] = 0.f;
    if (i == 0) g_nlist = 0;
}

// embW1 = emb(4096x128) @ W1(128x256). 16 vocab rows per block, 256 threads.
__global__ void k_embW1(const float* __restrict__ emb, const float* __restrict__ W1) {
    __shared__ float se[16 * EMB_DIM];        // 8 KB
    int b = blockIdx.x;                        // 256 blocks
    int t = threadIdx.x;                       // 256 threads (output col)
    for (int i = t; i < 16 * EMB_DIM; i += 256)
        se[i] = emb[b * 16 * EMB_DIM + i];
    __syncthreads();
    float acc[16];
#pragma unroll
    for (int r = 0; r < 16; ++r) acc[r] = 0.f;
    for (int k = 0; k < EMB_DIM; k += 4) {
        float w0 = W1[(k + 0) * H2 + t];
        float w1 = W1[(k + 1) * H2 + t];
        float w2 = W1[(k + 2) * H2 + t];
        float w3 = W1[(k + 3) * H2 + t];
#pragma unroll
        for (int r = 0; r < 16; ++r) {
            float4 s = *reinterpret_cast<const float4*>(&se[r * EMB_DIM + k]);
            acc[r] += s.x * w0 + s.y * w1 + s.z * w2 + s.w * w3;
        }
    }
#pragma unroll
    for (int r = 0; r < 16; ++r)
        g_embW1[(b * 16 + r) * H2 + t] = acc[r];
}

// deg count over col endpoints + position multiplicity flags.
__global__ void k_degsel(const int* __restrict__ ei, const int* __restrict__ pos) {
    int e = blockIdx.x * blockDim.x + threadIdx.x;
    if (e < N_EDGES) {
        atomicAdd(&g_deg[ei[N_EDGES + e]], 1);
    } else if (e < N_EDGES + N_POS) {
        atomicAdd(&g_selcnt[pos[e - N_EDGES]], 1);
    }
}

// coef[row] += dinv_row * dinv_col * selcnt[col] / N_POS for each edge into a
// selected node; plus self-loop terms for each position (handles duplicates).
__global__ void k_coefscan(const int* __restrict__ ei, const int* __restrict__ pos) {
    int e = blockIdx.x * blockDim.x + threadIdx.x;
    if (e < N_EDGES) {
        int c = ei[N_EDGES + e];
        int sc = g_selcnt[c];
        if (sc) {
            int r = ei[e];
            float w = rsqrtf((float)(g_deg[r] + 1)) * rsqrtf((float)(g_deg[c] + 1));
            atomicAdd(&g_coef[r], w * (float)sc * INVP);
        }
    } else if (e < N_EDGES + N_POS) {
        int v = pos[e - N_EDGES];
        float dv = rsqrtf((float)(g_deg[v] + 1));
        atomicAdd(&g_coef[v], dv * dv * INVP);
    }
}

__global__ void k_compact() {
    int v = blockIdx.x * blockDim.x + threadIdx.x;
    if (v < N_NODES && g_coef[v] != 0.f) {
        int idx = atomicAdd(&g_nlist, 1);
        g_list[idx] = v;
        g_needidx[v] = idx;
    }
}

// Single-block exclusive scan over degrees of the compacted list.
__global__ void k_scan_small() {
    __shared__ int s[1024];
    __shared__ int carry;
    int t = threadIdx.x;
    if (t == 0) carry = 0;
    __syncthreads();
    int n = g_nlist;
    for (int base = 0; base < n; base += 1024) {
        int i = base + t;
        int d = (i < n) ? g_deg[g_list[i]] : 0;
        s[t] = d;
        __syncthreads();
        for (int o = 1; o < 1024; o <<= 1) {
            int tmp = (t >= o) ? s[t - o] : 0;
            __syncthreads();
            s[t] += tmp;
            __syncthreads();
        }
        if (i < n) g_noff[i] = carry + s[t] - d;   // exclusive
        int total = s[1023];
        __syncthreads();
        if (t == 0) carry += total;
        __syncthreads();
    }
    if (t == 0) g_noff[n] = carry;
}

// Scatter ONLY edges whose target is a needed node into the mini-CSR.
__global__ void k_scatter2(const int* __restrict__ ei, const int* __restrict__ x) {
    int e = blockIdx.x * blockDim.x + threadIdx.x;
    if (e >= N_EDGES) return;
    int c = ei[N_EDGES + e];
    int idx = g_needidx[c];
    if (idx >= 0) {
        int r = ei[e];
        int p = g_noff[idx] + atomicAdd(&g_cur[idx], 1);
        g_xrow2[p] = x[r];
        g_w2[p] = rsqrtf((float)(g_deg[r] + 1)) * rsqrtf((float)(g_deg[c] + 1));
    }
}

// Grid-stride over needed nodes: h1[v] = relu(agg + self + b1) in registers,
// accumulate c_v * h1 locally across nodes, one atomic set per block at end.
__global__ void k_h1abar(const int* __restrict__ x, const float* __restrict__ b1) {
    __shared__ int   sxr[64];
    __shared__ float sw[64];
    int t = threadIdx.x;                      // 64 threads, float4 over 256 dims
    float4 bb = *reinterpret_cast<const float4*>(&b1[4 * t]);
    float4 tot = make_float4(0.f, 0.f, 0.f, 0.f);
    int n = g_nlist;
    for (int li = blockIdx.x; li < n; li += gridDim.x) {
        int v = g_list[li];
        float cv = g_coef[v];
        int beg = g_noff[li], end = g_noff[li + 1];
        float4 acc = make_float4(0.f, 0.f, 0.f, 0.f);
        for (int base = beg; base < end; base += 64) {
            int m = min(64, end - base);
            __syncthreads();
            if (t < m) { sxr[t] = g_xrow2[base + t]; sw[t] = g_w2[base + t]; }
            __syncthreads();
            int i = 0;
            for (; i + 2 <= m; i += 2) {
                float4 e0 = *reinterpret_cast<const float4*>(&g_embW1[sxr[i] * H2 + 4 * t]);
                float4 e1 = *reinterpret_cast<const float4*>(&g_embW1[sxr[i + 1] * H2 + 4 * t]);
                float w0 = sw[i], w1 = sw[i + 1];
                acc.x += e0.x * w0; acc.y += e0.y * w0; acc.z += e0.z * w0; acc.w += e0.w * w0;
                acc.x += e1.x * w1; acc.y += e1.y * w1; acc.z += e1.z * w1; acc.w += e1.w * w1;
            }
            if (i < m) {
                float4 e0 = *reinterpret_cast<const float4*>(&g_embW1[sxr[i] * H2 + 4 * t]);
                float w0 = sw[i];
                acc.x += e0.x * w0; acc.y += e0.y * w0; acc.z += e0.z * w0; acc.w += e0.w * w0;
            }
        }
        // self loop
        float dv = rsqrtf((float)(g_deg[v] + 1));
        float sl = dv * dv;
        float4 es = *reinterpret_cast<const float4*>(&g_embW1[x[v] * H2 + 4 * t]);
        acc.x += es.x * sl; acc.y += es.y * sl; acc.z += es.z * sl; acc.w += es.w * sl;
        tot.x += fmaxf(acc.x + bb.x, 0.f) * cv;
        tot.y += fmaxf(acc.y + bb.y, 0.f) * cv;
        tot.z += fmaxf(acc.z + bb.z, 0.f) * cv;
        tot.w += fmaxf(acc.w + bb.w, 0.f) * cv;
    }
    float* dst = &g_abarp[(blockIdx.x & (NPART - 1)) * H2 + 4 * t];
    atomicAdd(dst + 0, tot.x);
    atomicAdd(dst + 1, tot.y);
    atomicAdd(dst + 2, tot.z);
    atomicAdd(dst + 3, tot.w);
}

// Reduce partials, then zbar = abar @ W2 + b2   (256x128 matvec)
__global__ void k_finalA(const float* __restrict__ W2, const float* __restrict__ b2) {
    __shared__ float sabar[H2];
    int t = threadIdx.x;                      // 256
    float s = 0.f;
#pragma unroll 8
    for (int p = 0; p < NPART; ++p)
        s += g_abarp[p * H2 + t];
    sabar[t] = s;
    __syncthreads();
    if (t < HIDDEN) {
        float acc = b2[t];
#pragma unroll 8
        for (int k = 0; k < H2; ++k)
            acc += sabar[k] * W2[k * HIDDEN + t];
        g_zbar[t] = acc;
    }
}

// out = zbar @ Wc + bc    (128x4096 matvec)
__global__ void k_finalB(const float* __restrict__ Wc, const float* __restrict__ bc,
                         float* __restrict__ out) {
    __shared__ float sz[HIDDEN];
    int t = threadIdx.x;
    int c = blockIdx.x * 256 + t;
    if (t < HIDDEN) sz[t] = g_zbar[t];
    __syncthreads();
    float acc = bc[c];
#pragma unroll 8
    for (int j = 0; j < HIDDEN; ++j)
        acc += sz[j] * Wc[j * VOCAB + c];
    out[c] = acc;
}

// ---------------- launch ------------------------------------------------------

extern "C" void kernel_launch(void* const* d_in, const int* in_sizes, int n_in,
                              void* d_out, int out_size) {
    const int*   x    = (const int*)  d_in[0];   // (N_NODES,1) int32
    const int*   ei   = (const int*)  d_in[1];   // (2,N_EDGES) int32
    const int*   pos  = (const int*)  d_in[2];   // (N_POS,)    int32
    const float* emb  = (const float*)d_in[3];   // (4096,128)
    const float* W1   = (const float*)d_in[4];   // (128,256)
    const float* b1   = (const float*)d_in[5];   // (256,)
    const float* W2   = (const float*)d_in[6];   // (256,128)
    const float* b2   = (const float*)d_in[7];   // (128,)
    const float* Wc   = (const float*)d_in[8];   // (128,4096)
    const float* bc   = (const float*)d_in[9];   // (4096,)
    float* out = (float*)d_out;                  // (1,4096)

    k_init<<<256, 256>>>();
    k_embW1<<<VOCAB / 16, 256>>>(emb, W1);
    k_degsel<<<(N_EDGES + N_POS + 255) / 256, 256>>>(ei, pos);
    k_coefscan<<<(N_EDGES + N_POS + 255) / 256, 256>>>(ei, pos);
    k_compact<<<(N_NODES + 255) / 256, 256>>>();
    k_scan_small<<<1, 1024>>>();
    k_scatter2<<<(N_EDGES + 255) / 256, 256>>>(ei, x);
    k_h1abar<<<AGG_GRID, 64>>>(x, b1);
    k_finalA<<<1, H2>>>(W2, b2);
    k_finalB<<<VOCAB / 256, 256>>>(Wc, bc, out);
}

// round 9
// speedup vs baseline: 1.8482x; 1.0658x over previous
#include <cuda_runtime.h>
#include <cuda_fp16.h>

#define N_NODES 50000
#define N_EDGES 800000
#define VOCAB   4096
#define EMB_DIM 128
#define H2      256      // 2*HIDDEN
#define HIDDEN  128
#define N_POS   1024
#define NPART   64
#define AGG_GRID 2048
#define INVP    (1.f / N_POS)

// ---------------- scratch (static device globals; no allocation) ------------
__device__ __align__(16) __half g_embW1h[VOCAB * H2];  // emb @ W1, fp16 (2 MB)
__device__ int   g_deg[N_NODES];
__device__ int   g_selcnt[N_NODES];          // multiplicity of node in pos[]
__device__ int   g_needflag[N_NODES];
__device__ float g_coef[N_NODES];            // sparse coefficients c[u]
__device__ int   g_needidx[N_NODES];         // node -> compact idx, or -1
__device__ int   g_list[N_NODES];            // compacted needed nodes
__device__ int   g_nbase[N_NODES];           // CSR base (unordered alloc)
__device__ int   g_cur[N_NODES];             // per-needed-node fill cursor
__device__ int   g_nlist;
__device__ int   g_etotal;
__device__ int   g_nsel;
__device__ int   g_sele[N_EDGES];            // edge ids with selected target
__device__ int   g_xrow2[N_EDGES];           // vocab id of source, needed edges
__device__ float g_w2[N_EDGES];              // edge weight, needed edges
__device__ float g_abarp[NPART * H2];        // partial abar accumulators

// ---------------- kernels ----------------------------------------------------

__global__ void k_init() {
    int i = blockIdx.x * blockDim.x + threadIdx.x;
    int stride = gridDim.x * blockDim.x;
    for (int j = i; j < N_NODES; j += stride) {
        g_deg[j] = 0; g_selcnt[j] = 0; g_coef[j] = 0.f;
        g_needflag[j] = 0; g_needidx[j] = -1; g_cur[j] = 0;
    }
    for (int j = i; j < NPART * H2; j += stride) g_abarp[j] = 0.f;
    if (i == 0) { g_nlist = 0; g_etotal = 0; g_nsel = 0; }
}

// embW1 = emb(4096x128) @ W1(128x256), stored fp16.
// Block 0 additionally marks selected positions (completes before pass1).
__global__ void k_embW1(const float* __restrict__ emb, const float* __restrict__ W1,
                        const int* __restrict__ pos) {
    __shared__ float se[16 * EMB_DIM];        // 8 KB
    int b = blockIdx.x;                        // 256 blocks
    int t = threadIdx.x;                       // 256 threads (output col)
    if (b == 0) {
        for (int i = t; i < N_POS; i += 256) {
            int v = pos[i];
            atomicAdd(&g_selcnt[v], 1);
            g_needflag[v] = 1;
        }
    }
    for (int i = t; i < 16 * EMB_DIM; i += 256)
        se[i] = emb[b * 16 * EMB_DIM + i];
    __syncthreads();
    float acc[16];
#pragma unroll
    for (int r = 0; r < 16; ++r) acc[r] = 0.f;
    for (int k = 0; k < EMB_DIM; k += 4) {
        float w0 = W1[(k + 0) * H2 + t];
        float w1 = W1[(k + 1) * H2 + t];
        float w2 = W1[(k + 2) * H2 + t];
        float w3 = W1[(k + 3) * H2 + t];
#pragma unroll
        for (int r = 0; r < 16; ++r) {
            float4 s = *reinterpret_cast<const float4*>(&se[r * EMB_DIM + k]);
            acc[r] += s.x * w0 + s.y * w1 + s.z * w2 + s.w * w3;
        }
    }
#pragma unroll
    for (int r = 0; r < 16; ++r)
        g_embW1h[(b * 16 + r) * H2 + t] = __float2half(acc[r]);
}

// Pass 1: degree count + gather edges whose target is selected, flag sources.
__global__ void k_pass1(const int* __restrict__ ei) {
    int e = blockIdx.x * blockDim.x + threadIdx.x;
    if (e >= N_EDGES) return;
    int c = ei[N_EDGES + e];
    atomicAdd(&g_deg[c], 1);
    if (g_selcnt[c]) {
        int r = ei[e];
        g_needflag[r] = 1;
        int i = atomicAdd(&g_nsel, 1);
        g_sele[i] = e;
    }
}

// Coefficients from the small gathered list + self-loop terms per position.
__global__ void k_coef(const int* __restrict__ ei, const int* __restrict__ pos) {
    int tid = blockIdx.x * blockDim.x + threadIdx.x;
    int stride = gridDim.x * blockDim.x;
    int ns = g_nsel;
    for (int i = tid; i < ns + N_POS; i += stride) {
        if (i < ns) {
            int e = g_sele[i];
            int r = ei[e], c = ei[N_EDGES + e];
            float w = rsqrtf((float)(g_deg[r] + 1)) * rsqrtf((float)(g_deg[c] + 1));
            atomicAdd(&g_coef[r], w * (float)g_selcnt[c] * INVP);
        } else {
            int v = pos[i - ns];
            float dv = rsqrtf((float)(g_deg[v] + 1));
            atomicAdd(&g_coef[v], dv * dv * INVP);
        }
    }
}

// Compact needed nodes; allocate unordered CSR regions via atomic bump.
__global__ void k_compact() {
    int v = blockIdx.x * blockDim.x + threadIdx.x;
    if (v < N_NODES && g_needflag[v]) {
        int idx = atomicAdd(&g_nlist, 1);
        g_list[idx] = v;
        g_needidx[v] = idx;
        g_nbase[idx] = atomicAdd(&g_etotal, g_deg[v]);
    }
}

// Scatter ONLY edges whose target is a needed node into the mini-CSR.
__global__ void k_scatter2(const int* __restrict__ ei, const int* __restrict__ x) {
    int e = blockIdx.x * blockDim.x + threadIdx.x;
    if (e >= N_EDGES) return;
    int c = ei[N_EDGES + e];
    int idx = g_needidx[c];
    if (idx >= 0) {
        int r = ei[e];
        int p = g_nbase[idx] + atomicAdd(&g_cur[idx], 1);
        g_xrow2[p] = x[r];
        g_w2[p] = rsqrtf((float)(g_deg[r] + 1)) * rsqrtf((float)(g_deg[c] + 1));
    }
}

// Per needed node: h1 = relu(agg + self + b1) in registers (fp16 table,
// warp-shfl edge broadcast), accumulate c_v*h1 locally, one atomic set/block.
__global__ void k_h1abar(const int* __restrict__ x, const float* __restrict__ b1) {
    int lane = threadIdx.x;                    // 32 threads; lane owns 8 dims
    float4 bb0 = reinterpret_cast<const float4*>(b1)[lane * 2];
    float4 bb1 = reinterpret_cast<const float4*>(b1)[lane * 2 + 1];
    float tot[8];
#pragma unroll
    for (int d = 0; d < 8; ++d) tot[d] = 0.f;
    const uint4* tab = reinterpret_cast<const uint4*>(g_embW1h);
    int n = g_nlist;
    for (int li = blockIdx.x; li < n; li += gridDim.x) {
        int v = g_list[li];
        int beg = g_nbase[li];
        int end = beg + g_deg[v];
        float acc[8];
#pragma unroll
        for (int d = 0; d < 8; ++d) acc[d] = 0.f;
        for (int base = beg; base < end; base += 32) {
            int m = min(32, end - base);
            int xr = 0; float wv = 0.f;
            if (lane < m) { xr = g_xrow2[base + lane]; wv = g_w2[base + lane]; }
            for (int i = 0; i < m; ++i) {
                int   r = __shfl_sync(0xffffffffu, xr, i);
                float w = __shfl_sync(0xffffffffu, wv, i);
                uint4 q = tab[r * 32 + lane];
                const __half2* h = reinterpret_cast<const __half2*>(&q);
                float2 f0 = __half22float2(h[0]);
                float2 f1 = __half22float2(h[1]);
                float2 f2 = __half22float2(h[2]);
                float2 f3 = __half22float2(h[3]);
                acc[0] += f0.x * w; acc[1] += f0.y * w;
                acc[2] += f1.x * w; acc[3] += f1.y * w;
                acc[4] += f2.x * w; acc[5] += f2.y * w;
                acc[6] += f3.x * w; acc[7] += f3.y * w;
            }
        }
        // self loop
        float dv = rsqrtf((float)(g_deg[v] + 1));
        float sl = dv * dv;
        {
            uint4 q = tab[x[v] * 32 + lane];
            const __half2* h = reinterpret_cast<const __half2*>(&q);
            float2 f0 = __half22float2(h[0]);
            float2 f1 = __half22float2(h[1]);
            float2 f2 = __half22float2(h[2]);
            float2 f3 = __half22float2(h[3]);
            acc[0] += f0.x * sl; acc[1] += f0.y * sl;
            acc[2] += f1.x * sl; acc[3] += f1.y * sl;
            acc[4] += f2.x * sl; acc[5] += f2.y * sl;
            acc[6] += f3.x * sl; acc[7] += f3.y * sl;
        }
        float cv = g_coef[v];
        tot[0] += fmaxf(acc[0] + bb0.x, 0.f) * cv;
        tot[1] += fmaxf(acc[1] + bb0.y, 0.f) * cv;
        tot[2] += fmaxf(acc[2] + bb0.z, 0.f) * cv;
        tot[3] += fmaxf(acc[3] + bb0.w, 0.f) * cv;
        tot[4] += fmaxf(acc[4] + bb1.x, 0.f) * cv;
        tot[5] += fmaxf(acc[5] + bb1.y, 0.f) * cv;
        tot[6] += fmaxf(acc[6] + bb1.z, 0.f) * cv;
        tot[7] += fmaxf(acc[7] + bb1.w, 0.f) * cv;
    }
    float* dst = &g_abarp[(blockIdx.x & (NPART - 1)) * H2 + lane * 8];
#pragma unroll
    for (int d = 0; d < 8; ++d) atomicAdd(dst + d, tot[d]);
}

// Fused tail: reduce abar partials, zbar = abar@W2+b2 (recomputed per block),
// out slice = zbar@Wc + bc. 16 blocks x 256 threads.
__global__ void k_final(const float* __restrict__ W2, const float* __restrict__ b2,
                        const float* __restrict__ Wc, const float* __restrict__ bc,
                        float* __restrict__ out) {
    __shared__ float sabar[H2];
    __shared__ float sz[HIDDEN];
    int t = threadIdx.x;
    float s = 0.f;
#pragma unroll 8
    for (int p = 0; p < NPART; ++p)
        s += g_abarp[p * H2 + t];
    sabar[t] = s;
    __syncthreads();
    if (t < HIDDEN) {
        float acc = b2[t];
#pragma unroll 8
        for (int k = 0; k < H2; ++k)
            acc += sabar[k] * W2[k * HIDDEN + t];
        sz[t] = acc;
    }
    __syncthreads();
    int c = blockIdx.x * 256 + t;
    float acc = bc[c];
#pragma unroll 8
    for (int j = 0; j < HIDDEN; ++j)
        acc += sz[j] * Wc[j * VOCAB + c];
    out[c] = acc;
}

// ---------------- launch ------------------------------------------------------

extern "C" void kernel_launch(void* const* d_in, const int* in_sizes, int n_in,
                              void* d_out, int out_size) {
    const int*   x    = (const int*)  d_in[0];   // (N_NODES,1) int32
    const int*   ei   = (const int*)  d_in[1];   // (2,N_EDGES) int32
    const int*   pos  = (const int*)  d_in[2];   // (N_POS,)    int32
    const float* emb  = (const float*)d_in[3];   // (4096,128)
    const float* W1   = (const float*)d_in[4];   // (128,256)
    const float* b1   = (const float*)d_in[5];   // (256,)
    const float* W2   = (const float*)d_in[6];   // (256,128)
    const float* b2   = (const float*)d_in[7];   // (128,)
    const float* Wc   = (const float*)d_in[8];   // (128,4096)
    const float* bc   = (const float*)d_in[9];   // (4096,)
    float* out = (float*)d_out;                  // (1,4096)

    k_init<<<256, 256>>>();
    k_embW1<<<VOCAB / 16, 256>>>(emb, W1, pos);
    k_pass1<<<(N_EDGES + 255) / 256, 256>>>(ei);
    k_coef<<<64, 256>>>(ei, pos);
    k_compact<<<(N_NODES + 255) / 256, 256>>>();
    k_scatter2<<<(N_EDGES + 255) / 256, 256>>>(ei, x);
    k_h1abar<<<AGG_GRID, 32>>>(x, b1);
    k_final<<<VOCAB / 256, 256>>>(W2, b2, Wc, bc, out);
}

// round 12
// speedup vs baseline: 1.9705x; 1.0662x over previous
#include <cuda_runtime.h>
#include <cuda_fp16.h>

#define N_NODES 50000
#define N_EDGES 800000
#define VOCAB   4096
#define EMB_DIM 128
#define H2      256      // 2*HIDDEN
#define HIDDEN  128
#define N_POS   1024
#define NPART   64
#define AGG_GRID 2048
#define INVP    (1.f / N_POS)

// ---- single contiguous zero-init scratch region (one memset clears all) ----
#define CLR_DEG      0                        // int[N_NODES]
#define CLR_SELCNT   (CLR_DEG + N_NODES)      // int[N_NODES]
#define CLR_NEEDFLAG (CLR_SELCNT + N_NODES)   // int[N_NODES]
#define CLR_NIDX1    (CLR_NEEDFLAG + N_NODES) // int[N_NODES]  (idx+1; 0 = none)
#define CLR_CUR      (CLR_NIDX1 + N_NODES)    // int[N_NODES]
#define CLR_COEF     (CLR_CUR + N_NODES)      // float[N_NODES]
#define CLR_ABARP    (CLR_COEF + N_NODES)     // float[NPART*H2]
#define CLR_NLIST    (CLR_ABARP + NPART * H2)
#define CLR_ETOTAL   (CLR_NLIST + 1)
#define CLR_NSEL     (CLR_ETOTAL + 1)
#define CLR_TOTAL    (CLR_NSEL + 1)

__device__ __align__(16) int g_clr[CLR_TOTAL];

#define D_DEG      (g_clr + CLR_DEG)
#define D_SELCNT   (g_clr + CLR_SELCNT)
#define D_NEEDFLAG (g_clr + CLR_NEEDFLAG)
#define D_NIDX1    (g_clr + CLR_NIDX1)
#define D_CUR      (g_clr + CLR_CUR)
#define D_COEF     ((float*)(g_clr + CLR_COEF))
#define D_ABARP    ((float*)(g_clr + CLR_ABARP))
#define D_NLIST    (g_clr + CLR_NLIST)
#define D_ETOTAL   (g_clr + CLR_ETOTAL)
#define D_NSEL     (g_clr + CLR_NSEL)

// ---- non-cleared scratch ----
__device__ __align__(16) __half g_embW1h[VOCAB * H2];  // emb @ W1, fp16 (2 MB)
__device__ int   g_list[N_NODES];            // compacted needed nodes
__device__ int   g_nbase[N_NODES];           // CSR base (unordered alloc)
__device__ int   g_sele[N_EDGES];            // edge ids with selected target
__device__ int   g_xrow2[N_EDGES];           // vocab id of source, needed edges
__device__ float g_w2[N_EDGES];              // edge weight, needed edges

// ---------------- kernels ----------------------------------------------------

// Mark selected positions (tiny; runs right after memset).
__global__ void k_mark(const int* __restrict__ pos) {
    int i = blockIdx.x * blockDim.x + threadIdx.x;
    if (i < N_POS) {
        int v = pos[i];
        atomicAdd(&D_SELCNT[v], 1);
        D_NEEDFLAG[v] = 1;
    }
}

// Fused: blocks [0,256) compute embW1 = emb @ W1 (fp16 out);
// blocks [256, ...) do the edge pass: deg count + gather selected-target edges
// + flag their sources. The two halves are independent and overlap.
#define EMB_BLKS 256
#define EDGE_BLKS ((N_EDGES / 4 + 255) / 256)
__global__ void k_big(const float* __restrict__ emb, const float* __restrict__ W1,
                      const int* __restrict__ ei) {
    __shared__ float se[16 * EMB_DIM];        // 8 KB
    int b = blockIdx.x;
    int t = threadIdx.x;
    if (b < EMB_BLKS) {
        for (int i = t; i < 16 * EMB_DIM; i += 256)
            se[i] = emb[b * 16 * EMB_DIM + i];
        __syncthreads();
        float acc[16];
#pragma unroll
        for (int r = 0; r < 16; ++r) acc[r] = 0.f;
        for (int k = 0; k < EMB_DIM; k += 4) {
            float w0 = W1[(k + 0) * H2 + t];
            float w1 = W1[(k + 1) * H2 + t];
            float w2 = W1[(k + 2) * H2 + t];
            float w3 = W1[(k + 3) * H2 + t];
#pragma unroll
            for (int r = 0; r < 16; ++r) {
                float4 s = *reinterpret_cast<const float4*>(&se[r * EMB_DIM + k]);
                acc[r] += s.x * w0 + s.y * w1 + s.z * w2 + s.w * w3;
            }
        }
#pragma unroll
        for (int r = 0; r < 16; ++r)
            g_embW1h[(b * 16 + r) * H2 + t] = __float2half(acc[r]);
    } else {
        int e4 = ((b - EMB_BLKS) * 256 + t) * 4;
        if (e4 >= N_EDGES) return;
        int4 c4 = *reinterpret_cast<const int4*>(&ei[N_EDGES + e4]);
        int cs[4] = {c4.x, c4.y, c4.z, c4.w};
#pragma unroll
        for (int k = 0; k < 4; ++k) {
            int c = cs[k];
            atomicAdd(&D_DEG[c], 1);
            if (D_SELCNT[c]) {
                int r = ei[e4 + k];
                D_NEEDFLAG[r] = 1;
                int i = atomicAdd(D_NSEL, 1);
                g_sele[i] = e4 + k;
            }
        }
    }
}

// Fused coef + compact. Grid-stride over N_NODES (compact) then nsel+N_POS (coef).
__global__ void k_coefcompact(const int* __restrict__ ei, const int* __restrict__ pos) {
    int tid = blockIdx.x * blockDim.x + threadIdx.x;
    int stride = gridDim.x * blockDim.x;
    int ns = *D_NSEL;
    int total = N_NODES + ns + N_POS;
    for (int i = tid; i < total; i += stride) {
        if (i < N_NODES) {
            if (D_NEEDFLAG[i]) {
                int idx = atomicAdd(D_NLIST, 1);
                g_list[idx] = i;
                D_NIDX1[i] = idx + 1;
                g_nbase[idx] = atomicAdd(D_ETOTAL, D_DEG[i]);
            }
        } else if (i < N_NODES + ns) {
            int e = g_sele[i - N_NODES];
            int r = ei[e], c = ei[N_EDGES + e];
            float w = rsqrtf((float)(D_DEG[r] + 1)) * rsqrtf((float)(D_DEG[c] + 1));
            atomicAdd(&D_COEF[r], w * (float)D_SELCNT[c] * INVP);
        } else {
            int v = pos[i - N_NODES - ns];
            float dv = rsqrtf((float)(D_DEG[v] + 1));
            atomicAdd(&D_COEF[v], dv * dv * INVP);
        }
    }
}

// Scatter ONLY edges whose target is a needed node into the mini-CSR. int4 x4.
__global__ void k_scatter2(const int* __restrict__ ei, const int* __restrict__ x) {
    int e4 = (blockIdx.x * blockDim.x + threadIdx.x) * 4;
    if (e4 >= N_EDGES) return;
    int4 c4 = *reinterpret_cast<const int4*>(&ei[N_EDGES + e4]);
    int cs[4] = {c4.x, c4.y, c4.z, c4.w};
#pragma unroll
    for (int k = 0; k < 4; ++k) {
        int c = cs[k];
        int idx1 = D_NIDX1[c];
        if (idx1) {
            int idx = idx1 - 1;
            int r = ei[e4 + k];
            int p = g_nbase[idx] + atomicAdd(&D_CUR[idx], 1);
            g_xrow2[p] = x[r];
            g_w2[p] = rsqrtf((float)(D_DEG[r] + 1)) * rsqrtf((float)(D_DEG[c] + 1));
        }
    }
}

// Per needed node: h1 = relu(agg + self + b1) in registers (fp16 table,
// warp-shfl edge broadcast), accumulate c_v*h1 locally, one atomic set/block.
__global__ void k_h1abar(const int* __restrict__ x, const float* __restrict__ b1) {
    int lane = threadIdx.x;                    // 32 threads; lane owns 8 dims
    float4 bb0 = reinterpret_cast<const float4*>(b1)[lane * 2];
    float4 bb1 = reinterpret_cast<const float4*>(b1)[lane * 2 + 1];
    float tot[8];
#pragma unroll
    for (int d = 0; d < 8; ++d) tot[d] = 0.f;
    const uint4* tab = reinterpret_cast<const uint4*>(g_embW1h);
    int n = *D_NLIST;
    for (int li = blockIdx.x; li < n; li += gridDim.x) {
        int v = g_list[li];
        int beg = g_nbase[li];
        int end = beg + D_DEG[v];
        float acc[8];
#pragma unroll
        for (int d = 0; d < 8; ++d) acc[d] = 0.f;
        for (int base = beg; base < end; base += 32) {
            int m = min(32, end - base);
            int xr = 0; float wv = 0.f;
            if (lane < m) { xr = g_xrow2[base + lane]; wv = g_w2[base + lane]; }
            for (int i = 0; i < m; ++i) {
                int   r = __shfl_sync(0xffffffffu, xr, i);
                float w = __shfl_sync(0xffffffffu, wv, i);
                uint4 q = tab[r * 32 + lane];
                const __half2* h = reinterpret_cast<const __half2*>(&q);
                float2 f0 = __half22float2(h[0]);
                float2 f1 = __half22float2(h[1]);
                float2 f2 = __half22float2(h[2]);
                float2 f3 = __half22float2(h[3]);
                acc[0] += f0.x * w; acc[1] += f0.y * w;
                acc[2] += f1.x * w; acc[3] += f1.y * w;
                acc[4] += f2.x * w; acc[5] += f2.y * w;
                acc[6] += f3.x * w; acc[7] += f3.y * w;
            }
        }
        // self loop
        float dv = rsqrtf((float)(D_DEG[v] + 1));
        float sl = dv * dv;
        {
            uint4 q = tab[x[v] * 32 + lane];
            const __half2* h = reinterpret_cast<const __half2*>(&q);
            float2 f0 = __half22float2(h[0]);
            float2 f1 = __half22float2(h[1]);
            float2 f2 = __half22float2(h[2]);
            float2 f3 = __half22float2(h[3]);
            acc[0] += f0.x * sl; acc[1] += f0.y * sl;
            acc[2] += f1.x * sl; acc[3] += f1.y * sl;
            acc[4] += f2.x * sl; acc[5] += f2.y * sl;
            acc[6] += f3.x * sl; acc[7] += f3.y * sl;
        }
        float cv = D_COEF[v];
        tot[0] += fmaxf(acc[0] + bb0.x, 0.f) * cv;
        tot[1] += fmaxf(acc[1] + bb0.y, 0.f) * cv;
        tot[2] += fmaxf(acc[2] + bb0.z, 0.f) * cv;
        tot[3] += fmaxf(acc[3] + bb0.w, 0.f) * cv;
        tot[4] += fmaxf(acc[4] + bb1.x, 0.f) * cv;
        tot[5] += fmaxf(acc[5] + bb1.y, 0.f) * cv;
        tot[6] += fmaxf(acc[6] + bb1.z, 0.f) * cv;
        tot[7] += fmaxf(acc[7] + bb1.w, 0.f) * cv;
    }
    float* dst = &D_ABARP[(blockIdx.x & (NPART - 1)) * H2 + lane * 8];
#pragma unroll
    for (int d = 0; d < 8; ++d) atomicAdd(dst + d, tot[d]);
}

// Fused tail: reduce abar partials, zbar = abar@W2+b2 (recomputed per block),
// out slice = zbar@Wc + bc. 16 blocks x 256 threads.
__global__ void k_final(const float* __restrict__ W2, const float* __restrict__ b2,
                        const float* __restrict__ Wc, const float* __restrict__ bc,
                        float* __restrict__ out) {
    __shared__ float sabar[H2];
    __shared__ float sz[HIDDEN];
    int t = threadIdx.x;
    float s = 0.f;
#pragma unroll 8
    for (int p = 0; p < NPART; ++p)
        s += D_ABARP[p * H2 + t];
    sabar[t] = s;
    __syncthreads();
    if (t < HIDDEN) {
        float acc = b2[t];
#pragma unroll 8
        for (int k = 0; k < H2; ++k)
            acc += sabar[k] * W2[k * HIDDEN + t];
        sz[t] = acc;
    }
    __syncthreads();
    int c = blockIdx.x * 256 + t;
    float acc = bc[c];
#pragma unroll 8
    for (int j = 0; j < HIDDEN; ++j)
        acc += sz[j] * Wc[j * VOCAB + c];
    out[c] = acc;
}

// ---------------- launch ------------------------------------------------------

extern "C" void kernel_launch(void* const* d_in, const int* in_sizes, int n_in,
                              void* d_out, int out_size) {
    const int*   x    = (const int*)  d_in[0];   // (N_NODES,1) int32
    const int*   ei   = (const int*)  d_in[1];   // (2,N_EDGES) int32
    const int*   pos  = (const int*)  d_in[2];   // (N_POS,)    int32
    const float* emb  = (const float*)d_in[3];   // (4096,128)
    const float* W1   = (const float*)d_in[4];   // (128,256)
    const float* b1   = (const float*)d_in[5];   // (256,)
    const float* W2   = (const float*)d_in[6];   // (256,128)
    const float* b2   = (const float*)d_in[7];   // (128,)
    const float* Wc   = (const float*)d_in[8];   // (128,4096)
    const float* bc   = (const float*)d_in[9];   // (4096,)
    float* out = (float*)d_out;                  // (1,4096)

    void* clrp = nullptr;
    cudaGetSymbolAddress(&clrp, g_clr);
    cudaMemsetAsync(clrp, 0, CLR_TOTAL * sizeof(int));

    k_mark<<<(N_POS + 255) / 256, 256>>>(pos);
    k_big<<<EMB_BLKS + EDGE_BLKS, 256>>>(emb, W1, ei);
    k_coefcompact<<<512, 256>>>(ei, pos);
    k_scatter2<<<(N_EDGES / 4 + 255) / 256, 256>>>(ei, x);
    k_h1abar<<<AGG_GRID, 32>>>(x, b1);
    k_final<<<VOCAB / 256, 256>>>(W2, b2, Wc, bc, out);
}

// round 13
// speedup vs baseline: 2.1035x; 1.0675x over previous
#include <cuda_runtime.h>
#include <cuda_fp16.h>

#define N_NODES 50000
#define N_EDGES 800000
#define VOCAB   4096
#define EMB_DIM 128
#define H2      256      // 2*HIDDEN
#define HIDDEN  128
#define N_POS   1024
#define NPART   64
#define AGG_GRID 2048
#define INVP    (1.f / N_POS)
#define BMW     ((N_NODES + 31) / 32)

// ---- single contiguous zero-init scratch region (one memset clears all) ----
#define CLR_DEG      0                        // int[N_NODES]
#define CLR_SELCNT   (CLR_DEG + N_NODES)      // int[N_NODES]
#define CLR_NIDX1    (CLR_SELCNT + N_NODES)   // int[N_NODES]  (idx+1; 0 = none)
#define CLR_CUR      (CLR_NIDX1 + N_NODES)    // int[N_NODES]
#define CLR_COEF     (CLR_CUR + N_NODES)      // float[N_NODES]
#define CLR_ABARP    (CLR_COEF + N_NODES)     // float[NPART*H2]
#define CLR_SELBM    (CLR_ABARP + NPART * H2) // uint[BMW]
#define CLR_NEEDBM   (CLR_SELBM + BMW)        // uint[BMW]
#define CLR_NLIST    (CLR_NEEDBM + BMW)
#define CLR_ETOTAL   (CLR_NLIST + 1)
#define CLR_NSEL     (CLR_ETOTAL + 1)
#define CLR_TOTAL    (CLR_NSEL + 1)

__device__ __align__(16) int g_clr[CLR_TOTAL];

#define D_DEG      (g_clr + CLR_DEG)
#define D_SELCNT   (g_clr + CLR_SELCNT)
#define D_NIDX1    (g_clr + CLR_NIDX1)
#define D_CUR      (g_clr + CLR_CUR)
#define D_COEF     ((float*)(g_clr + CLR_COEF))
#define D_ABARP    ((float*)(g_clr + CLR_ABARP))
#define D_SELBM    ((unsigned*)(g_clr + CLR_SELBM))
#define D_NEEDBM   ((unsigned*)(g_clr + CLR_NEEDBM))
#define D_NLIST    (g_clr + CLR_NLIST)
#define D_ETOTAL   (g_clr + CLR_ETOTAL)
#define D_NSEL     (g_clr + CLR_NSEL)

// ---- non-cleared scratch ----
__device__ __align__(16) __half g_embW1h[VOCAB * H2];  // emb @ W1, fp16 (2 MB)
__device__ int      g_list[N_NODES];         // compacted needed nodes
__device__ int      g_nbase[N_NODES];        // CSR base (unordered alloc)
__device__ unsigned g_px[N_NODES];           // ((deg+1)<<12) | x  per node
__device__ int      g_sele[N_EDGES];         // edge ids with selected target
__device__ unsigned g_pk[N_EDGES];           // packed (deg_r+1)<<12|x_r per needed edge

// ---------------- kernels ----------------------------------------------------

// Mark selected positions: multiplicity + selected bitmap + needed bitmap.
__global__ void k_mark(const int* __restrict__ pos) {
    int i = blockIdx.x * blockDim.x + threadIdx.x;
    if (i < N_POS) {
        int v = pos[i];
        atomicAdd(&D_SELCNT[v], 1);
        atomicOr(&D_SELBM[v >> 5], 1u << (v & 31));
        atomicOr(&D_NEEDBM[v >> 5], 1u << (v & 31));
    }
}

// Fused: blocks [0,256) compute embW1 = emb @ W1 (fp16 out);
// blocks [256, ...) do the edge pass: deg count + gather selected-target edges
// (bitmap test, L1-resident) + flag their sources in the needed bitmap.
#define EMB_BLKS 256
#define EDGE_BLKS ((N_EDGES / 4 + 255) / 256)
__global__ void k_big(const float* __restrict__ emb, const float* __restrict__ W1,
                      const int* __restrict__ ei) {
    __shared__ float se[16 * EMB_DIM];        // 8 KB
    int b = blockIdx.x;
    int t = threadIdx.x;
    if (b < EMB_BLKS) {
        for (int i = t; i < 16 * EMB_DIM; i += 256)
            se[i] = emb[b * 16 * EMB_DIM + i];
        __syncthreads();
        float acc[16];
#pragma unroll
        for (int r = 0; r < 16; ++r) acc[r] = 0.f;
        for (int k = 0; k < EMB_DIM; k += 4) {
            float w0 = W1[(k + 0) * H2 + t];
            float w1 = W1[(k + 1) * H2 + t];
            float w2 = W1[(k + 2) * H2 + t];
            float w3 = W1[(k + 3) * H2 + t];
#pragma unroll
            for (int r = 0; r < 16; ++r) {
                float4 s = *reinterpret_cast<const float4*>(&se[r * EMB_DIM + k]);
                acc[r] += s.x * w0 + s.y * w1 + s.z * w2 + s.w * w3;
            }
        }
#pragma unroll
        for (int r = 0; r < 16; ++r)
            g_embW1h[(b * 16 + r) * H2 + t] = __float2half(acc[r]);
    } else {
        int e4 = ((b - EMB_BLKS) * 256 + t) * 4;
        if (e4 >= N_EDGES) return;
        int4 c4 = *reinterpret_cast<const int4*>(&ei[N_EDGES + e4]);
        int cs[4] = {c4.x, c4.y, c4.z, c4.w};
#pragma unroll
        for (int k = 0; k < 4; ++k) {
            int c = cs[k];
            atomicAdd(&D_DEG[c], 1);
            if (D_SELBM[c >> 5] & (1u << (c & 31))) {      // L1-resident bitmap
                int r = ei[e4 + k];
                atomicOr(&D_NEEDBM[r >> 5], 1u << (r & 31));
                int i = atomicAdd(D_NSEL, 1);
                g_sele[i] = e4 + k;
            }
        }
    }
}

// Fused: per-node pack px + compact needed nodes + coef terms.
__global__ void k_coefcompact(const int* __restrict__ ei, const int* __restrict__ pos,
                              const int* __restrict__ x) {
    int tid = blockIdx.x * blockDim.x + threadIdx.x;
    int stride = gridDim.x * blockDim.x;
    int ns = *D_NSEL;
    int total = N_NODES + ns + N_POS;
    for (int i = tid; i < total; i += stride) {
        if (i < N_NODES) {
            int d = D_DEG[i];
            g_px[i] = ((unsigned)(d + 1) << 12) | (unsigned)x[i];
            if (D_NEEDBM[i >> 5] & (1u << (i & 31))) {
                int idx = atomicAdd(D_NLIST, 1);
                g_list[idx] = i;
                D_NIDX1[i] = idx + 1;
                g_nbase[idx] = atomicAdd(D_ETOTAL, d);
            }
        } else if (i < N_NODES + ns) {
            int e = g_sele[i - N_NODES];
            int r = ei[e], c = ei[N_EDGES + e];
            float w = rsqrtf((float)(D_DEG[r] + 1)) * rsqrtf((float)(D_DEG[c] + 1));
            atomicAdd(&D_COEF[r], w * (float)D_SELCNT[c] * INVP);
        } else {
            int v = pos[i - N_NODES - ns];
            float dv = rsqrtf((float)(D_DEG[v] + 1));
            atomicAdd(&D_COEF[v], dv * dv * INVP);
        }
    }
}

// Scatter ONLY edges whose target is needed (bitmap reject path = L1 hit).
// Per needed edge: one random load (px[r]) + one 4-byte write.
__global__ void k_scatter2(const int* __restrict__ ei) {
    int e4 = (blockIdx.x * blockDim.x + threadIdx.x) * 4;
    if (e4 >= N_EDGES) return;
    int4 c4 = *reinterpret_cast<const int4*>(&ei[N_EDGES + e4]);
    int cs[4] = {c4.x, c4.y, c4.z, c4.w};
#pragma unroll
    for (int k = 0; k < 4; ++k) {
        int c = cs[k];
        if (D_NEEDBM[c >> 5] & (1u << (c & 31))) {
            int idx = D_NIDX1[c] - 1;
            int r = ei[e4 + k];
            int p = g_nbase[idx] + atomicAdd(&D_CUR[idx], 1);
            g_pk[p] = g_px[r];
        }
    }
}

// Per needed node v: acc = sum_e dinv_r * e_r + dv * e_self (all weights local),
// h1 = relu(acc*dv + b1); tot += c_v * h1. 32 threads, lane owns 8 dims.
__global__ void k_h1abar(const float* __restrict__ b1) {
    int lane = threadIdx.x;
    float4 bb0 = reinterpret_cast<const float4*>(b1)[lane * 2];
    float4 bb1 = reinterpret_cast<const float4*>(b1)[lane * 2 + 1];
    float tot[8];
#pragma unroll
    for (int d = 0; d < 8; ++d) tot[d] = 0.f;
    const uint4* tab = reinterpret_cast<const uint4*>(g_embW1h);
    int n = *D_NLIST;
    for (int li = blockIdx.x; li < n; li += gridDim.x) {
        int v = g_list[li];
        unsigned pv = g_px[v];
        float dv = rsqrtf((float)(pv >> 12));
        int deg = (int)(pv >> 12) - 1;
        int beg = g_nbase[li];
        int end = beg + deg;
        float acc[8];
#pragma unroll
        for (int d = 0; d < 8; ++d) acc[d] = 0.f;
        for (int base = beg; base < end; base += 32) {
            int m = min(32, end - base);
            int xr = 0; float wv = 0.f;
            if (lane < m) {
                unsigned pk = g_pk[base + lane];
                xr = (int)(pk & 0xFFFu);
                wv = rsqrtf((float)(pk >> 12));
            }
            int i = 0;
            for (; i + 4 <= m; i += 4) {
                int   r0 = __shfl_sync(0xffffffffu, xr, i);
                int   r1 = __shfl_sync(0xffffffffu, xr, i + 1);
                int   r2 = __shfl_sync(0xffffffffu, xr, i + 2);
                int   r3 = __shfl_sync(0xffffffffu, xr, i + 3);
                float w0 = __shfl_sync(0xffffffffu, wv, i);
                float w1 = __shfl_sync(0xffffffffu, wv, i + 1);
                float w2 = __shfl_sync(0xffffffffu, wv, i + 2);
                float w3 = __shfl_sync(0xffffffffu, wv, i + 3);
                uint4 q0 = tab[r0 * 32 + lane];
                uint4 q1 = tab[r1 * 32 + lane];
                uint4 q2 = tab[r2 * 32 + lane];
                uint4 q3 = tab[r3 * 32 + lane];
#pragma unroll
                for (int u = 0; u < 4; ++u) {
                    uint4 q = (u == 0) ? q0 : (u == 1) ? q1 : (u == 2) ? q2 : q3;
                    float w = (u == 0) ? w0 : (u == 1) ? w1 : (u == 2) ? w2 : w3;
                    const __half2* h = reinterpret_cast<const __half2*>(&q);
                    float2 f0 = __half22float2(h[0]);
                    float2 f1 = __half22float2(h[1]);
                    float2 f2 = __half22float2(h[2]);
                    float2 f3 = __half22float2(h[3]);
                    acc[0] += f0.x * w; acc[1] += f0.y * w;
                    acc[2] += f1.x * w; acc[3] += f1.y * w;
                    acc[4] += f2.x * w; acc[5] += f2.y * w;
                    acc[6] += f3.x * w; acc[7] += f3.y * w;
                }
            }
            for (; i < m; ++i) {
                int   r = __shfl_sync(0xffffffffu, xr, i);
                float w = __shfl_sync(0xffffffffu, wv, i);
                uint4 q = tab[r * 32 + lane];
                const __half2* h = reinterpret_cast<const __half2*>(&q);
                float2 f0 = __half22float2(h[0]);
                float2 f1 = __half22float2(h[1]);
                float2 f2 = __half22float2(h[2]);
                float2 f3 = __half22float2(h[3]);
                acc[0] += f0.x * w; acc[1] += f0.y * w;
                acc[2] += f1.x * w; acc[3] += f1.y * w;
                acc[4] += f2.x * w; acc[5] += f2.y * w;
                acc[6] += f3.x * w; acc[7] += f3.y * w;
            }
        }
        // self loop: acc += dv * e_self, then h1 = acc*dv + b1
        {
            int xv = (int)(pv & 0xFFFu);
            uint4 q = tab[xv * 32 + lane];
            const __half2* h = reinterpret_cast<const __half2*>(&q);
            float2 f0 = __half22float2(h[0]);
            float2 f1 = __half22float2(h[1]);
            float2 f2 = __half22float2(h[2]);
            float2 f3 = __half22float2(h[3]);
            acc[0] += f0.x * dv; acc[1] += f0.y * dv;
            acc[2] += f1.x * dv; acc[3] += f1.y * dv;
            acc[4] += f2.x * dv; acc[5] += f2.y * dv;
            acc[6] += f3.x * dv; acc[7] += f3.y * dv;
        }
        float cv = D_COEF[v];
        tot[0] += fmaxf(acc[0] * dv + bb0.x, 0.f) * cv;
        tot[1] += fmaxf(acc[1] * dv + bb0.y, 0.f) * cv;
        tot[2] += fmaxf(acc[2] * dv + bb0.z, 0.f) * cv;
        tot[3] += fmaxf(acc[3] * dv + bb0.w, 0.f) * cv;
        tot[4] += fmaxf(acc[4] * dv + bb1.x, 0.f) * cv;
        tot[5] += fmaxf(acc[5] * dv + bb1.y, 0.f) * cv;
        tot[6] += fmaxf(acc[6] * dv + bb1.z, 0.f) * cv;
        tot[7] += fmaxf(acc[7] * dv + bb1.w, 0.f) * cv;
    }
    float* dst = &D_ABARP[(blockIdx.x & (NPART - 1)) * H2 + lane * 8];
#pragma unroll
    for (int d = 0; d < 8; ++d) atomicAdd(dst + d, tot[d]);
}

// Fused tail: reduce abar partials, zbar = abar@W2+b2 (recomputed per block),
// out slice = zbar@Wc + bc. 16 blocks x 256 threads.
__global__ void k_final(const float* __restrict__ W2, const float* __restrict__ b2,
                        const float* __restrict__ Wc, const float* __restrict__ bc,
                        float* __restrict__ out) {
    __shared__ float sabar[H2];
    __shared__ float sz[HIDDEN];
    int t = threadIdx.x;
    float s = 0.f;
#pragma unroll 8
    for (int p = 0; p < NPART; ++p)
        s += D_ABARP[p * H2 + t];
    sabar[t] = s;
    __syncthreads();
    if (t < HIDDEN) {
        float acc = b2[t];
#pragma unroll 8
        for (int k = 0; k < H2; ++k)
            acc += sabar[k] * W2[k * HIDDEN + t];
        sz[t] = acc;
    }
    __syncthreads();
    int c = blockIdx.x * 256 + t;
    float acc = bc[c];
#pragma unroll 8
    for (int j = 0; j < HIDDEN; ++j)
        acc += sz[j] * Wc[j * VOCAB + c];
    out[c] = acc;
}

// ---------------- launch ------------------------------------------------------

extern "C" void kernel_launch(void* const* d_in, const int* in_sizes, int n_in,
                              void* d_out, int out_size) {
    const int*   x    = (const int*)  d_in[0];   // (N_NODES,1) int32
    const int*   ei   = (const int*)  d_in[1];   // (2,N_EDGES) int32
    const int*   pos  = (const int*)  d_in[2];   // (N_POS,)    int32
    const float* emb  = (const float*)d_in[3];   // (4096,128)
    const float* W1   = (const float*)d_in[4];   // (128,256)
    const float* b1   = (const float*)d_in[5];   // (256,)
    const float* W2   = (const float*)d_in[6];   // (256,128)
    const float* b2   = (const float*)d_in[7];   // (128,)
    const float* Wc   = (const float*)d_in[8];   // (128,4096)
    const float* bc   = (const float*)d_in[9];   // (4096,)
    float* out = (float*)d_out;                  // (1,4096)

    void* clrp = nullptr;
    cudaGetSymbolAddress(&clrp, g_clr);
    cudaMemsetAsync(clrp, 0, CLR_TOTAL * sizeof(int));

    k_mark<<<(N_POS + 255) / 256, 256>>>(pos);
    k_big<<<EMB_BLKS + EDGE_BLKS, 256>>>(emb, W1, ei);
    k_coefcompact<<<512, 256>>>(ei, pos, x);
    k_scatter2<<<(N_EDGES / 4 + 255) / 256, 256>>>(ei);
    k_h1abar<<<AGG_GRID, 32>>>(b1);
    k_final<<<VOCAB / 256, 256>>>(W2, b2, Wc, bc, out);
}

// round 14
// speedup vs baseline: 2.2064x; 1.0489x over previous
#include <cuda_runtime.h>
#include <cuda_fp16.h>

#define N_NODES 50000
#define N_EDGES 800000
#define VOCAB   4096
#define EMB_DIM 128
#define H2      256      // 2*HIDDEN
#define HIDDEN  128
#define N_POS   1024
#define NPART   64
#define AGG_GRID 2048
#define INVP    (1.f / N_POS)
#define BMW     ((N_NODES + 31) / 32)

// ---- single contiguous zero-init scratch region (one memset clears all) ----
#define CLR_DEG      0                        // int[N_NODES]
#define CLR_SELCNT   (CLR_DEG + N_NODES)      // int[N_NODES]
#define CLR_CUR      (CLR_SELCNT + N_NODES)   // int[N_NODES] (CSR fill cursor, preset to base)
#define CLR_COEF     (CLR_CUR + N_NODES)      // float[N_NODES]
#define CLR_ABARP    (CLR_COEF + N_NODES)     // float[NPART*H2]
#define CLR_SELBM    (CLR_ABARP + NPART * H2) // uint[BMW]
#define CLR_NEEDBM   (CLR_SELBM + BMW)        // uint[BMW]
#define CLR_NLIST    (CLR_NEEDBM + BMW)
#define CLR_ETOTAL   (CLR_NLIST + 1)
#define CLR_NSEL     (CLR_ETOTAL + 1)
#define CLR_TOTAL    (CLR_NSEL + 1)

__device__ __align__(16) int g_clr[CLR_TOTAL];

#define D_DEG      (g_clr + CLR_DEG)
#define D_SELCNT   (g_clr + CLR_SELCNT)
#define D_CUR      (g_clr + CLR_CUR)
#define D_COEF     ((float*)(g_clr + CLR_COEF))
#define D_ABARP    ((float*)(g_clr + CLR_ABARP))
#define D_SELBM    ((unsigned*)(g_clr + CLR_SELBM))
#define D_NEEDBM   ((unsigned*)(g_clr + CLR_NEEDBM))
#define D_NLIST    (g_clr + CLR_NLIST)
#define D_ETOTAL   (g_clr + CLR_ETOTAL)
#define D_NSEL     (g_clr + CLR_NSEL)

// ---- non-cleared scratch ----
__device__ __align__(16) __half g_embW1h[VOCAB * H2];  // emb @ W1, fp16 (2 MB)
__device__ int      g_list[N_NODES];         // compacted needed nodes
__device__ int      g_nbase[N_NODES];        // CSR base per compact idx
__device__ unsigned g_px[N_NODES];           // ((deg+1)<<12) | x  per node
__device__ int      g_sele[N_EDGES];         // edge ids with selected target
__device__ unsigned g_pk[N_EDGES];           // packed (deg_r+1)<<12|x_r per needed edge

// ---------------- kernels ----------------------------------------------------

// Mark selected positions: multiplicity + selected bitmap + needed bitmap.
__global__ void k_mark(const int* __restrict__ pos) {
    int i = blockIdx.x * blockDim.x + threadIdx.x;
    if (i < N_POS) {
        int v = pos[i];
        atomicAdd(&D_SELCNT[v], 1);
        atomicOr(&D_SELBM[v >> 5], 1u << (v & 31));
        atomicOr(&D_NEEDBM[v >> 5], 1u << (v & 31));
    }
}

// Fused: blocks [0,256) compute embW1 = emb @ W1 (fp16 out);
// blocks [256, ...) do the edge pass: deg count + gather selected-target edges
// (bitmap test, L1-resident) + flag their sources in the needed bitmap.
#define EMB_BLKS 256
#define EDGE_BLKS ((N_EDGES / 4 + 255) / 256)
__global__ void k_big(const float* __restrict__ emb, const float* __restrict__ W1,
                      const int* __restrict__ ei) {
    __shared__ float se[16 * EMB_DIM];        // 8 KB
    int b = blockIdx.x;
    int t = threadIdx.x;
    if (b < EMB_BLKS) {
        for (int i = t; i < 16 * EMB_DIM; i += 256)
            se[i] = emb[b * 16 * EMB_DIM + i];
        __syncthreads();
        float acc[16];
#pragma unroll
        for (int r = 0; r < 16; ++r) acc[r] = 0.f;
        for (int k = 0; k < EMB_DIM; k += 4) {
            float w0 = W1[(k + 0) * H2 + t];
            float w1 = W1[(k + 1) * H2 + t];
            float w2 = W1[(k + 2) * H2 + t];
            float w3 = W1[(k + 3) * H2 + t];
#pragma unroll
            for (int r = 0; r < 16; ++r) {
                float4 s = *reinterpret_cast<const float4*>(&se[r * EMB_DIM + k]);
                acc[r] += s.x * w0 + s.y * w1 + s.z * w2 + s.w * w3;
            }
        }
#pragma unroll
        for (int r = 0; r < 16; ++r)
            g_embW1h[(b * 16 + r) * H2 + t] = __float2half(acc[r]);
    } else {
        int e4 = ((b - EMB_BLKS) * 256 + t) * 4;
        if (e4 >= N_EDGES) return;
        int4 c4 = *reinterpret_cast<const int4*>(&ei[N_EDGES + e4]);
        int cs[4] = {c4.x, c4.y, c4.z, c4.w};
#pragma unroll
        for (int k = 0; k < 4; ++k) {
            int c = cs[k];
            atomicAdd(&D_DEG[c], 1);
            if (D_SELBM[c >> 5] & (1u << (c & 31))) {      // L1-resident bitmap
                int r = ei[e4 + k];
                atomicOr(&D_NEEDBM[r >> 5], 1u << (r & 31));
                int i = atomicAdd(D_NSEL, 1);
                g_sele[i] = e4 + k;
            }
        }
    }
}

// Fused: per-node pack px + compact needed nodes (cursor preset to CSR base)
// + coef terms from the gathered selected-target edge list.
__global__ void k_coefcompact(const int* __restrict__ ei, const int* __restrict__ pos,
                              const int* __restrict__ x) {
    int tid = blockIdx.x * blockDim.x + threadIdx.x;
    int stride = gridDim.x * blockDim.x;
    int ns = *D_NSEL;
    int total = N_NODES + ns + N_POS;
    for (int i = tid; i < total; i += stride) {
        if (i < N_NODES) {
            int d = D_DEG[i];
            g_px[i] = ((unsigned)(d + 1) << 12) | (unsigned)x[i];
            if (D_NEEDBM[i >> 5] & (1u << (i & 31))) {
                int idx = atomicAdd(D_NLIST, 1);
                g_list[idx] = i;
                int base = atomicAdd(D_ETOTAL, d);
                g_nbase[idx] = base;
                D_CUR[i] = base;               // cursor starts at CSR base
            }
        } else if (i < N_NODES + ns) {
            int e = g_sele[i - N_NODES];
            int r = ei[e], c = ei[N_EDGES + e];
            float w = rsqrtf((float)(D_DEG[r] + 1)) * rsqrtf((float)(D_DEG[c] + 1));
            atomicAdd(&D_COEF[r], w * (float)D_SELCNT[c] * INVP);
        } else {
            int v = pos[i - N_NODES - ns];
            float dv = rsqrtf((float)(D_DEG[v] + 1));
            atomicAdd(&D_COEF[v], dv * dv * INVP);
        }
    }
}

// Scatter edges whose target is needed. Per accepted edge: ONE random atomic
// (cursor-at-base, returns slot), one random px[r] load, one 4-byte write.
__global__ void k_scatter2(const int* __restrict__ ei) {
    int e4 = (blockIdx.x * blockDim.x + threadIdx.x) * 4;
    if (e4 >= N_EDGES) return;
    int4 c4 = *reinterpret_cast<const int4*>(&ei[N_EDGES + e4]);
    int4 r4 = *reinterpret_cast<const int4*>(&ei[e4]);
    int cs[4] = {c4.x, c4.y, c4.z, c4.w};
    int rs[4] = {r4.x, r4.y, r4.z, r4.w};
#pragma unroll
    for (int k = 0; k < 4; ++k) {
        int c = cs[k];
        if (D_NEEDBM[c >> 5] & (1u << (c & 31))) {
            int p = atomicAdd(&D_CUR[c], 1);
            g_pk[p] = g_px[rs[k]];
        }
    }
}

// Per needed node v: acc = sum_e dinv_r * e_r + dv * e_self,
// h1 = relu(acc*dv + b1); tot += c_v * h1. 32 threads, lane owns 8 dims.
__global__ void k_h1abar(const float* __restrict__ b1) {
    int lane = threadIdx.x;
    float4 bb0 = reinterpret_cast<const float4*>(b1)[lane * 2];
    float4 bb1 = reinterpret_cast<const float4*>(b1)[lane * 2 + 1];
    float tot[8];
#pragma unroll
    for (int d = 0; d < 8; ++d) tot[d] = 0.f;
    const uint4* tab = reinterpret_cast<const uint4*>(g_embW1h);
    int n = *D_NLIST;
    for (int li = blockIdx.x; li < n; li += gridDim.x) {
        int v = g_list[li];
        unsigned pv = g_px[v];
        float dv = rsqrtf((float)(pv >> 12));
        int deg = (int)(pv >> 12) - 1;
        int beg = g_nbase[li];
        int end = beg + deg;
        float acc[8];
#pragma unroll
        for (int d = 0; d < 8; ++d) acc[d] = 0.f;
        for (int base = beg; base < end; base += 32) {
            int m = min(32, end - base);
            int xr = 0; float wv = 0.f;
            if (lane < m) {
                unsigned pk = g_pk[base + lane];
                xr = (int)(pk & 0xFFFu);
                wv = rsqrtf((float)(pk >> 12));
            }
            int i = 0;
            for (; i + 8 <= m; i += 8) {          // MLP = 8
                int rr[8]; float ww[8]; uint4 q[8];
#pragma unroll
                for (int u = 0; u < 8; ++u) {
                    rr[u] = __shfl_sync(0xffffffffu, xr, i + u);
                    ww[u] = __shfl_sync(0xffffffffu, wv, i + u);
                }
#pragma unroll
                for (int u = 0; u < 8; ++u) q[u] = tab[rr[u] * 32 + lane];
#pragma unroll
                for (int u = 0; u < 8; ++u) {
                    const __half2* h = reinterpret_cast<const __half2*>(&q[u]);
                    float w = ww[u];
                    float2 f0 = __half22float2(h[0]);
                    float2 f1 = __half22float2(h[1]);
                    float2 f2 = __half22float2(h[2]);
                    float2 f3 = __half22float2(h[3]);
                    acc[0] += f0.x * w; acc[1] += f0.y * w;
                    acc[2] += f1.x * w; acc[3] += f1.y * w;
                    acc[4] += f2.x * w; acc[5] += f2.y * w;
                    acc[6] += f3.x * w; acc[7] += f3.y * w;
                }
            }
            for (; i < m; ++i) {
                int   r = __shfl_sync(0xffffffffu, xr, i);
                float w = __shfl_sync(0xffffffffu, wv, i);
                uint4 q = tab[r * 32 + lane];
                const __half2* h = reinterpret_cast<const __half2*>(&q);
                float2 f0 = __half22float2(h[0]);
                float2 f1 = __half22float2(h[1]);
                float2 f2 = __half22float2(h[2]);
                float2 f3 = __half22float2(h[3]);
                acc[0] += f0.x * w; acc[1] += f0.y * w;
                acc[2] += f1.x * w; acc[3] += f1.y * w;
                acc[4] += f2.x * w; acc[5] += f2.y * w;
                acc[6] += f3.x * w; acc[7] += f3.y * w;
            }
        }
        // self loop: acc += dv * e_self, then h1 = acc*dv + b1
        {
            int xv = (int)(pv & 0xFFFu);
            uint4 q = tab[xv * 32 + lane];
            const __half2* h = reinterpret_cast<const __half2*>(&q);
            float2 f0 = __half22float2(h[0]);
            float2 f1 = __half22float2(h[1]);
            float2 f2 = __half22float2(h[2]);
            float2 f3 = __half22float2(h[3]);
            acc[0] += f0.x * dv; acc[1] += f0.y * dv;
            acc[2] += f1.x * dv; acc[3] += f1.y * dv;
            acc[4] += f2.x * dv; acc[5] += f2.y * dv;
            acc[6] += f3.x * dv; acc[7] += f3.y * dv;
        }
        float cv = D_COEF[v];
        tot[0] += fmaxf(acc[0] * dv + bb0.x, 0.f) * cv;
        tot[1] += fmaxf(acc[1] * dv + bb0.y, 0.f) * cv;
        tot[2] += fmaxf(acc[2] * dv + bb0.z, 0.f) * cv;
        tot[3] += fmaxf(acc[3] * dv + bb0.w, 0.f) * cv;
        tot[4] += fmaxf(acc[4] * dv + bb1.x, 0.f) * cv;
        tot[5] += fmaxf(acc[5] * dv + bb1.y, 0.f) * cv;
        tot[6] += fmaxf(acc[6] * dv + bb1.z, 0.f) * cv;
        tot[7] += fmaxf(acc[7] * dv + bb1.w, 0.f) * cv;
    }
    float* dst = &D_ABARP[(blockIdx.x & (NPART - 1)) * H2 + lane * 8];
#pragma unroll
    for (int d = 0; d < 8; ++d) atomicAdd(dst + d, tot[d]);
}

// Fused tail: reduce abar partials, zbar = abar@W2+b2 (recomputed per block),
// out slice = zbar@Wc + bc. 16 blocks x 256 threads.
__global__ void k_final(const float* __restrict__ W2, const float* __restrict__ b2,
                        const float* __restrict__ Wc, const float* __restrict__ bc,
                        float* __restrict__ out) {
    __shared__ float sabar[H2];
    __shared__ float sz[HIDDEN];
    int t = threadIdx.x;
    float s = 0.f;
#pragma unroll 8
    for (int p = 0; p < NPART; ++p)
        s += D_ABARP[p * H2 + t];
    sabar[t] = s;
    __syncthreads();
    if (t < HIDDEN) {
        float acc = b2[t];
#pragma unroll 8
        for (int k = 0; k < H2; ++k)
            acc += sabar[k] * W2[k * HIDDEN + t];
        sz[t] = acc;
    }
    __syncthreads();
    int c = blockIdx.x * 256 + t;
    float acc = bc[c];
#pragma unroll 8
    for (int j = 0; j < HIDDEN; ++j)
        acc += sz[j] * Wc[j * VOCAB + c];
    out[c] = acc;
}

// ---------------- launch ------------------------------------------------------

extern "C" void kernel_launch(void* const* d_in, const int* in_sizes, int n_in,
                              void* d_out, int out_size) {
    const int*   x    = (const int*)  d_in[0];   // (N_NODES,1) int32
    const int*   ei   = (const int*)  d_in[1];   // (2,N_EDGES) int32
    const int*   pos  = (const int*)  d_in[2];   // (N_POS,)    int32
    const float* emb  = (const float*)d_in[3];   // (4096,128)
    const float* W1   = (const float*)d_in[4];   // (128,256)
    const float* b1   = (const float*)d_in[5];   // (256,)
    const float* W2   = (const float*)d_in[6];   // (256,128)
    const float* b2   = (const float*)d_in[7];   // (128,)
    const float* Wc   = (const float*)d_in[8];   // (128,4096)
    const float* bc   = (const float*)d_in[9];   // (4096,)
    float* out = (float*)d_out;                  // (1,4096)

    void* clrp = nullptr;
    cudaGetSymbolAddress(&clrp, g_clr);
    cudaMemsetAsync(clrp, 0, CLR_TOTAL * sizeof(int));

    k_mark<<<(N_POS + 255) / 256, 256>>>(pos);
    k_big<<<EMB_BLKS + EDGE_BLKS, 256>>>(emb, W1, ei);
    k_coefcompact<<<512, 256>>>(ei, pos, x);
    k_scatter2<<<(N_EDGES / 4 + 255) / 256, 256>>>(ei);
    k_h1abar<<<AGG_GRID, 32>>>(b1);
    k_final<<<VOCAB / 256, 256>>>(W2, b2, Wc, bc, out);
}